// round 1
// baseline (speedup 1.0000x reference)
#include <cuda_runtime.h>
#include <math.h>
#include <stdint.h>

// Problem constants
#define B_    512
#define N_    64
#define H_    256
#define BN_   32768          // B_*N_
#define KX    768            // X = [inp(512) | h(256)]
#define NG    1024           // G columns: [r-sum 256 | i-sum 256 | i_n 256 | h_n 256]

// ---------------- device scratch (static, allocation-free) ----------------
__device__ float g_X[(size_t)BN_ * KX];        // [32768,768]
__device__ float g_hcat[(size_t)BN_ * 512];    // [32768,512] = [hin | hout]
__device__ float g_G[(size_t)BN_ * NG];        // [32768,1024]
__device__ float g_Wpack[NG * KX];             // packed big weight [1024,768]
__device__ float g_bpack[NG];
__device__ float g_Wcat[512 * H_];             // [W_in; W_out] rows
__device__ float g_bcat[512];

// ---------------- K0: pack weights/biases ----------------
__global__ void build_pack(const float* __restrict__ w_ih, const float* __restrict__ w_hh,
                           const float* __restrict__ b_ih, const float* __restrict__ b_hh,
                           const float* __restrict__ W_in, const float* __restrict__ b_in,
                           const float* __restrict__ W_out, const float* __restrict__ b_out)
{
    const int stride = gridDim.x * blockDim.x;
    const int idx = blockIdx.x * blockDim.x + threadIdx.x;

    // Wpack [1024, 768]
    for (int i = idx; i < NG * KX; i += stride) {
        int n = i / KX, k = i - n * KX;
        float v = 0.f;
        if (n < 512)      v = (k < 512) ? w_ih[n * 512 + k] : w_hh[n * 256 + (k - 512)];
        else if (n < 768) v = (k < 512) ? w_ih[n * 512 + k] : 0.f;
        else              v = (k >= 512) ? w_hh[(n - 256) * 256 + (k - 512)] : 0.f;
        g_Wpack[i] = v;
    }
    // Wcat [512, 256]
    for (int i = idx; i < 512 * H_; i += stride) {
        g_Wcat[i] = (i < 256 * H_) ? W_in[i] : W_out[i - 256 * H_];
    }
    // bpack
    for (int i = idx; i < NG; i += stride) {
        float bv;
        if (i < 512)      bv = b_ih[i] + b_hh[i];
        else if (i < 768) bv = b_ih[i];
        else              bv = b_hh[i - 256];
        g_bpack[i] = bv;
    }
    // bcat
    for (int i = idx; i < 512; i += stride)
        g_bcat[i] = (i < 256) ? b_in[i] : b_out[i - 256];
}

// ---------------- K1: embedding gather + L2 normalize -> g_X[:,512:768] ----
__global__ void __launch_bounds__(256) gather_norm(const int* __restrict__ inputs,
                                                   const float* __restrict__ emb)
{
    const int row = blockIdx.x;             // 0..32767
    const int t = threadIdx.x;              // 0..255
    const float* e = emb + (size_t)inputs[row] * H_;
    float v = e[t];
    float ss = v * v;
    #pragma unroll
    for (int o = 16; o > 0; o >>= 1) ss += __shfl_xor_sync(0xffffffffu, ss, o);
    __shared__ float ws[8];
    __shared__ float s_scale;
    if ((t & 31) == 0) ws[t >> 5] = ss;
    __syncthreads();
    if (t == 0) {
        float s = 0.f;
        #pragma unroll
        for (int i = 0; i < 8; i++) s += ws[i];
        s_scale = 1.f / (sqrtf(s) + 1e-12f);
    }
    __syncthreads();
    g_X[(size_t)row * KX + 512 + t] = v * s_scale;
}

// ---------------- generic fp32 SGEMM (NT): C[m,n] = sum_k A[m,k]*B[n,k] + bias[n]
// 128x128 tile, BK=8, 256 threads, 8x8 per thread.
__global__ void __launch_bounds__(256, 2) sgemm_nt(
    const float* __restrict__ Am, int lda,
    const float* __restrict__ Bm, int ldb,
    const float* __restrict__ bias,
    float* __restrict__ C, int ldc,
    int kBegin, int kEnd, int grouped)
{
    __shared__ float As[8][128];
    __shared__ float Bs[8][128];

    const int tid = threadIdx.x;
    const int m0 = blockIdx.x * 128;
    const int n0 = blockIdx.y * 128;

    int kb = kBegin, ke = kEnd;
    if (grouped) {
        if (n0 >= 768)      { kb = 512; ke = 768; }   // h_n : K over h part
        else if (n0 >= 512) { kb = 0;   ke = 512; }   // i_n : K over inp part
        else                { kb = 0;   ke = 768; }   // r/i sums : full K
    }

    const int ldRow = tid >> 1;              // 0..127
    const int ldCol = (tid & 1) * 4;         // 0 or 4
    const float* aPtr = Am + (size_t)(m0 + ldRow) * lda + ldCol;
    const float* bPtr = Bm + (size_t)(n0 + ldRow) * ldb + ldCol;

    const int tRow = (tid >> 4) * 8;
    const int tCol = (tid & 15) * 8;

    float acc[8][8];
    #pragma unroll
    for (int i = 0; i < 8; i++)
        #pragma unroll
        for (int j = 0; j < 8; j++) acc[i][j] = 0.f;

    for (int k0 = kb; k0 < ke; k0 += 8) {
        float4 av = *(const float4*)(aPtr + k0);
        float4 bv = *(const float4*)(bPtr + k0);
        As[ldCol + 0][ldRow] = av.x; As[ldCol + 1][ldRow] = av.y;
        As[ldCol + 2][ldRow] = av.z; As[ldCol + 3][ldRow] = av.w;
        Bs[ldCol + 0][ldRow] = bv.x; Bs[ldCol + 1][ldRow] = bv.y;
        Bs[ldCol + 2][ldRow] = bv.z; Bs[ldCol + 3][ldRow] = bv.w;
        __syncthreads();
        #pragma unroll
        for (int kk = 0; kk < 8; kk++) {
            float ar[8], br[8];
            *(float4*)&ar[0] = *(const float4*)&As[kk][tRow];
            *(float4*)&ar[4] = *(const float4*)&As[kk][tRow + 4];
            *(float4*)&br[0] = *(const float4*)&Bs[kk][tCol];
            *(float4*)&br[4] = *(const float4*)&Bs[kk][tCol + 4];
            #pragma unroll
            for (int i = 0; i < 8; i++)
                #pragma unroll
                for (int j = 0; j < 8; j++)
                    acc[i][j] += ar[i] * br[j];
        }
        __syncthreads();
    }

    float bb[8];
    #pragma unroll
    for (int j = 0; j < 8; j++) bb[j] = bias[n0 + tCol + j];

    #pragma unroll
    for (int i = 0; i < 8; i++) {
        float* crow = C + (size_t)(m0 + tRow + i) * ldc + n0 + tCol;
        float4 o0, o1;
        o0.x = acc[i][0] + bb[0]; o0.y = acc[i][1] + bb[1];
        o0.z = acc[i][2] + bb[2]; o0.w = acc[i][3] + bb[3];
        o1.x = acc[i][4] + bb[4]; o1.y = acc[i][5] + bb[5];
        o1.z = acc[i][6] + bb[6]; o1.w = acc[i][7] + bb[7];
        *(float4*)(crow) = o0;
        *(float4*)(crow + 4) = o1;
    }
}

// ---------------- K3: per-batch adjacency matmuls -> g_X[:,0:512] ----------
// input_in  = A[:, :, :64]  @ hin  + b_iah
// input_out = A[:, :, 64:]  @ hout + b_oah
__global__ void __launch_bounds__(256) adjacency_kernel(const float* __restrict__ Aadj,
                                                        const float* __restrict__ b_iah,
                                                        const float* __restrict__ b_oah)
{
    __shared__ float shA[64 * 64];    // 16 KB
    __shared__ float shH[64 * 128];   // 32 KB
    const int b = blockIdx.x;
    const int tid = threadIdx.x;
    const float* Ab = Aadj + (size_t)b * (64 * 128);
    const int r0 = b * 64;

    for (int half = 0; half < 2; half++) {
        const float* bias = half ? b_oah : b_iah;
        __syncthreads();  // prior compute finished reading shA
        for (int i = tid; i < 64 * 64; i += 256) {
            int n = i >> 6, m = i & 63;
            shA[i] = Ab[n * 128 + half * 64 + m];
        }
        for (int chunk = 0; chunk < 2; chunk++) {
            __syncthreads();  // prior compute finished reading shH
            for (int i = tid; i < 64 * 128; i += 256) {
                int m = i >> 7, c = i & 127;
                shH[i] = g_hcat[(size_t)(r0 + m) * 512 + half * 256 + chunk * 128 + c];
            }
            __syncthreads();
            // 64x128 outputs, 4x4 register tiles: 16 n-tiles * 32 c-tiles = 512 tiles
            for (int t = tid; t < 512; t += 256) {
                int n = (t >> 5) * 4;
                int c = (t & 31) * 4;
                float acc[4][4];
                #pragma unroll
                for (int i = 0; i < 4; i++)
                    #pragma unroll
                    for (int j = 0; j < 4; j++) acc[i][j] = 0.f;
                #pragma unroll 4
                for (int m = 0; m < 64; m++) {
                    float4 hv = *(const float4*)&shH[m * 128 + c];
                    float a0 = shA[(n + 0) * 64 + m];
                    float a1 = shA[(n + 1) * 64 + m];
                    float a2 = shA[(n + 2) * 64 + m];
                    float a3 = shA[(n + 3) * 64 + m];
                    acc[0][0] += a0 * hv.x; acc[0][1] += a0 * hv.y; acc[0][2] += a0 * hv.z; acc[0][3] += a0 * hv.w;
                    acc[1][0] += a1 * hv.x; acc[1][1] += a1 * hv.y; acc[1][2] += a1 * hv.z; acc[1][3] += a1 * hv.w;
                    acc[2][0] += a2 * hv.x; acc[2][1] += a2 * hv.y; acc[2][2] += a2 * hv.z; acc[2][3] += a2 * hv.w;
                    acc[3][0] += a3 * hv.x; acc[3][1] += a3 * hv.y; acc[3][2] += a3 * hv.z; acc[3][3] += a3 * hv.w;
                }
                int cc = chunk * 128 + c;     // column within H
                float b0 = bias[cc + 0], b1 = bias[cc + 1], b2 = bias[cc + 2], b3 = bias[cc + 3];
                #pragma unroll
                for (int i = 0; i < 4; i++) {
                    float4 o;
                    o.x = acc[i][0] + b0; o.y = acc[i][1] + b1;
                    o.z = acc[i][2] + b2; o.w = acc[i][3] + b3;
                    *(float4*)&g_X[(size_t)(r0 + n + i) * KX + half * 256 + cc] = o;
                }
            }
        }
    }
}

// ---------------- K5: gates epilogue -> out ----------------
__global__ void __launch_bounds__(256) gates_kernel(float* __restrict__ out)
{
    int idx = blockIdx.x * blockDim.x + threadIdx.x;
    if (idx >= BN_ * H_) return;
    int r = idx >> 8;        // / 256
    int c = idx & 255;
    const float* Gr = g_G + (size_t)r * NG;
    float sr  = Gr[c];            // i_r + h_r (+biases)
    float si  = Gr[256 + c];      // i_i + h_i
    float vin = Gr[512 + c];      // i_n
    float vhn = Gr[768 + c];      // h_n
    float h   = g_X[(size_t)r * KX + 512 + c];
    float rg = 1.f / (1.f + expf(-sr));
    float ig = 1.f / (1.f + expf(-si));
    float ng = tanhf(vin + rg * vhn);
    out[idx] = ng + ig * (h - ng);
}

// ---------------- launcher ----------------
extern "C" void kernel_launch(void* const* d_in, const int* in_sizes, int n_in,
                              void* d_out, int out_size)
{
    const int*   inputs = (const int*)  d_in[0];   // [512,64]
    const float* Aadj   = (const float*)d_in[1];   // [512,64,128]
    const float* emb    = (const float*)d_in[2];   // [100000,256]
    const float* W_in   = (const float*)d_in[3];
    const float* b_in   = (const float*)d_in[4];
    const float* W_out  = (const float*)d_in[5];
    const float* b_out  = (const float*)d_in[6];
    const float* w_ih   = (const float*)d_in[7];   // [768,512]
    const float* b_ih   = (const float*)d_in[8];
    const float* w_hh   = (const float*)d_in[9];   // [768,256]
    const float* b_hh   = (const float*)d_in[10];
    const float* b_iah  = (const float*)d_in[11];
    const float* b_oah  = (const float*)d_in[12];
    float* out = (float*)d_out;

    float *d_X, *d_hcat, *d_G, *d_Wpack, *d_bpack, *d_Wcat, *d_bcat;
    cudaGetSymbolAddress((void**)&d_X, g_X);
    cudaGetSymbolAddress((void**)&d_hcat, g_hcat);
    cudaGetSymbolAddress((void**)&d_G, g_G);
    cudaGetSymbolAddress((void**)&d_Wpack, g_Wpack);
    cudaGetSymbolAddress((void**)&d_bpack, g_bpack);
    cudaGetSymbolAddress((void**)&d_Wcat, g_Wcat);
    cudaGetSymbolAddress((void**)&d_bcat, g_bcat);

    // K0: pack weights
    build_pack<<<512, 256>>>(w_ih, w_hh, b_ih, b_hh, W_in, b_in, W_out, b_out);

    // K1: gather + normalize into X[:,512:768]
    gather_norm<<<BN_, 256>>>(inputs, emb);

    // K2: hcat = h @ Wcat^T + bcat   (M=32768, N=512, K=256)
    sgemm_nt<<<dim3(BN_ / 128, 512 / 128), 256>>>(
        d_X + 512, KX, d_Wcat, H_, d_bcat, d_hcat, 512, 0, 256, 0);

    // K3: adjacency -> X[:,0:512]
    adjacency_kernel<<<B_, 256>>>(Aadj, b_iah, b_oah);

    // K4: G = X @ Wpack^T + bpack   (grouped K ranges, M=32768, N=1024)
    sgemm_nt<<<dim3(BN_ / 128, NG / 128), 256>>>(
        d_X, KX, d_Wpack, KX, d_bpack, d_G, NG, 0, 0, 1);

    // K5: gates
    gates_kernel<<<(BN_ * H_ + 255) / 256, 256>>>(out);
}

// round 2
// speedup vs baseline: 2.4571x; 2.4571x over previous
#include <cuda_runtime.h>
#include <math.h>
#include <stdint.h>

// Problem constants
#define B_    512
#define N_    64
#define H_    256
#define BN_   32768          // B_*N_
#define KX    768            // X = [inp(512) | h(256)]
#define NG    1024           // G columns: [r-sum 256 | i-sum 256 | i_n 256 | h_n 256]

// ---------------- device scratch (static, allocation-free) ----------------
__device__ float g_X[(size_t)BN_ * KX];        // [32768,768]
__device__ float g_hcat[(size_t)BN_ * 512];    // [32768,512] = [hin | hout]
__device__ float g_G[(size_t)BN_ * NG];        // [32768,1024]
__device__ float g_Wpack[NG * KX];             // packed big weight [1024,768]
__device__ float g_bpack[NG];
__device__ float g_Wcat[512 * H_];             // [W_in; W_out] rows
__device__ float g_bcat[512];

__device__ __forceinline__ float tf32_rna(float x) {
    uint32_t u;
    asm("cvt.rna.tf32.f32 %0, %1;" : "=r"(u) : "f"(x));
    return __uint_as_float(u);
}

// ---------------- K0: pack weights/biases (tf32-rounded weights) ----------
__global__ void build_pack(const float* __restrict__ w_ih, const float* __restrict__ w_hh,
                           const float* __restrict__ b_ih, const float* __restrict__ b_hh,
                           const float* __restrict__ W_in, const float* __restrict__ b_in,
                           const float* __restrict__ W_out, const float* __restrict__ b_out)
{
    const int stride = gridDim.x * blockDim.x;
    const int idx = blockIdx.x * blockDim.x + threadIdx.x;

    // Wpack [1024, 768]
    for (int i = idx; i < NG * KX; i += stride) {
        int n = i / KX, k = i - n * KX;
        float v = 0.f;
        if (n < 512)      v = (k < 512) ? w_ih[n * 512 + k] : w_hh[n * 256 + (k - 512)];
        else if (n < 768) v = (k < 512) ? w_ih[n * 512 + k] : 0.f;
        else              v = (k >= 512) ? w_hh[(n - 256) * 256 + (k - 512)] : 0.f;
        g_Wpack[i] = tf32_rna(v);
    }
    // Wcat [512, 256]
    for (int i = idx; i < 512 * H_; i += stride) {
        float v = (i < 256 * H_) ? W_in[i] : W_out[i - 256 * H_];
        g_Wcat[i] = tf32_rna(v);
    }
    // bpack
    for (int i = idx; i < NG; i += stride) {
        float bv;
        if (i < 512)      bv = b_ih[i] + b_hh[i];
        else if (i < 768) bv = b_ih[i];
        else              bv = b_hh[i - 256];
        g_bpack[i] = bv;
    }
    // bcat
    for (int i = idx; i < 512; i += stride)
        g_bcat[i] = (i < 256) ? b_in[i] : b_out[i - 256];
}

// ---------------- K1: embedding gather + L2 normalize -> g_X[:,512:768] ----
__global__ void __launch_bounds__(256) gather_norm(const int* __restrict__ inputs,
                                                   const float* __restrict__ emb)
{
    const int row = blockIdx.x;             // 0..32767
    const int t = threadIdx.x;              // 0..255
    const float* e = emb + (size_t)inputs[row] * H_;
    float v = e[t];
    float ss = v * v;
    #pragma unroll
    for (int o = 16; o > 0; o >>= 1) ss += __shfl_xor_sync(0xffffffffu, ss, o);
    __shared__ float ws[8];
    __shared__ float s_scale;
    if ((t & 31) == 0) ws[t >> 5] = ss;
    __syncthreads();
    if (t == 0) {
        float s = 0.f;
        #pragma unroll
        for (int i = 0; i < 8; i++) s += ws[i];
        s_scale = 1.f / (sqrtf(s) + 1e-12f);
    }
    __syncthreads();
    g_X[(size_t)row * KX + 512 + t] = tf32_rna(v * s_scale);
}

// ---------------- cp.async helpers ----------------
__device__ __forceinline__ void cp_async16(float* smem_dst, const float* gmem_src) {
    uint32_t sa = (uint32_t)__cvta_generic_to_shared(smem_dst);
    asm volatile("cp.async.cg.shared.global [%0], [%1], 16;\n" :: "r"(sa), "l"(gmem_src));
}
__device__ __forceinline__ void cp_commit() { asm volatile("cp.async.commit_group;\n"); }
__device__ __forceinline__ void cp_wait0()  { asm volatile("cp.async.wait_group 0;\n" ::: "memory"); }

// ---------------- TF32 tensor-core GEMM (NT): C[m,n] = sum_k A[m,k]*B[n,k] + bias[n]
// CTA tile 128x128, BK=32, 256 threads (8 warps), warp tile 64x32 (4x4 of m16n8k8).
// Smem: row-major padded tiles, stride 36 floats (conflict-free frag loads).
#define SM_STRIDE 36
#define TILE_FLTS (128 * SM_STRIDE)          // 4608 floats per tile
#define STAGE_FLTS (2 * TILE_FLTS)           // A + B per stage

__global__ void __launch_bounds__(256, 2) mma_gemm_tf32(
    const float* __restrict__ Am, int lda,
    const float* __restrict__ Bm, int ldb,
    const float* __restrict__ bias,
    float* __restrict__ C, int ldc,
    int kBegin, int kEnd, int grouped)
{
    extern __shared__ float sm[];   // 2 stages * (As + Bs)

    const int tid = threadIdx.x;
    const int m0 = blockIdx.x * 128;
    const int n0 = blockIdx.y * 128;

    int kb = kBegin, ke = kEnd;
    if (grouped) {
        if (n0 >= 768)      { kb = 512; ke = 768; }   // h_n : K over h part
        else if (n0 >= 512) { kb = 0;   ke = 512; }   // i_n : K over inp part
        else                { kb = 0;   ke = 768; }   // r/i sums : full K
    }

    const int lane = tid & 31;
    const int g = lane >> 2;      // 0..7
    const int t = lane & 3;       // 0..3
    const int warpId = tid >> 5;
    const int wm = (warpId >> 2) * 64;   // 0 or 64
    const int wn = (warpId & 3) * 32;    // 0..96

    // global->smem load mapping: row = tid>>1 (0..127), 4 chunks of 16B
    const int ldr = tid >> 1;
    const int ldc4 = (tid & 1) * 16;     // float offset within 32-float row

    const float* gA = Am + (size_t)(m0 + ldr) * lda + ldc4;
    const float* gB = Bm + (size_t)(n0 + ldr) * ldb + ldc4;

    float acc[4][4][4];
    #pragma unroll
    for (int i = 0; i < 4; i++)
        #pragma unroll
        for (int j = 0; j < 4; j++)
            #pragma unroll
            for (int c = 0; c < 4; c++) acc[i][j][c] = 0.f;

    // prologue: stage 0
    {
        float* As = sm;
        float* Bs = sm + TILE_FLTS;
        #pragma unroll
        for (int j = 0; j < 4; j++) {
            cp_async16(As + ldr * SM_STRIDE + ldc4 + j * 4, gA + kb + j * 4);
            cp_async16(Bs + ldr * SM_STRIDE + ldc4 + j * 4, gB + kb + j * 4);
        }
        cp_commit();
    }

    int s = 0;
    for (int k0 = kb; k0 < ke; k0 += 32, s ^= 1) {
        cp_wait0();
        __syncthreads();

        const int kn = k0 + 32;
        if (kn < ke) {
            float* As = sm + (s ^ 1) * STAGE_FLTS;
            float* Bs = As + TILE_FLTS;
            #pragma unroll
            for (int j = 0; j < 4; j++) {
                cp_async16(As + ldr * SM_STRIDE + ldc4 + j * 4, gA + kn + j * 4);
                cp_async16(Bs + ldr * SM_STRIDE + ldc4 + j * 4, gB + kn + j * 4);
            }
            cp_commit();
        }

        const uint32_t* As = (const uint32_t*)(sm + s * STAGE_FLTS);
        const uint32_t* Bs = (const uint32_t*)(sm + s * STAGE_FLTS + TILE_FLTS);

        #pragma unroll
        for (int kk = 0; kk < 4; kk++) {
            const int k8 = kk * 8;
            uint32_t a[4][4];
            #pragma unroll
            for (int mt = 0; mt < 4; mt++) {
                const int row = wm + mt * 16 + g;
                a[mt][0] = As[row * SM_STRIDE + k8 + t];
                a[mt][1] = As[(row + 8) * SM_STRIDE + k8 + t];
                a[mt][2] = As[row * SM_STRIDE + k8 + t + 4];
                a[mt][3] = As[(row + 8) * SM_STRIDE + k8 + t + 4];
            }
            uint32_t b[4][2];
            #pragma unroll
            for (int nt = 0; nt < 4; nt++) {
                const int col = wn + nt * 8 + g;
                b[nt][0] = Bs[col * SM_STRIDE + k8 + t];
                b[nt][1] = Bs[col * SM_STRIDE + k8 + t + 4];
            }
            #pragma unroll
            for (int mt = 0; mt < 4; mt++)
                #pragma unroll
                for (int nt = 0; nt < 4; nt++) {
                    asm volatile(
                        "mma.sync.aligned.m16n8k8.row.col.f32.tf32.tf32.f32 "
                        "{%0,%1,%2,%3}, {%4,%5,%6,%7}, {%8,%9}, {%0,%1,%2,%3};\n"
                        : "+f"(acc[mt][nt][0]), "+f"(acc[mt][nt][1]),
                          "+f"(acc[mt][nt][2]), "+f"(acc[mt][nt][3])
                        : "r"(a[mt][0]), "r"(a[mt][1]), "r"(a[mt][2]), "r"(a[mt][3]),
                          "r"(b[nt][0]), "r"(b[nt][1]));
                }
        }
        __syncthreads();
    }

    // epilogue: bias add + store
    #pragma unroll
    for (int nt = 0; nt < 4; nt++) {
        const int col = n0 + wn + nt * 8 + t * 2;
        const float b0 = bias[col], b1 = bias[col + 1];
        #pragma unroll
        for (int mt = 0; mt < 4; mt++) {
            const int row = m0 + wm + mt * 16 + g;
            float2 o0, o1;
            o0.x = acc[mt][nt][0] + b0; o0.y = acc[mt][nt][1] + b1;
            o1.x = acc[mt][nt][2] + b0; o1.y = acc[mt][nt][3] + b1;
            *(float2*)(C + (size_t)row * ldc + col) = o0;
            *(float2*)(C + (size_t)(row + 8) * ldc + col) = o1;
        }
    }
}

// ---------------- K3: per-batch adjacency matmuls -> g_X[:,0:512] ----------
__global__ void __launch_bounds__(256) adjacency_kernel(const float* __restrict__ Aadj,
                                                        const float* __restrict__ b_iah,
                                                        const float* __restrict__ b_oah)
{
    __shared__ float shA[64 * 64];    // 16 KB
    __shared__ float shH[64 * 128];   // 32 KB
    const int b = blockIdx.x;
    const int tid = threadIdx.x;
    const float* Ab = Aadj + (size_t)b * (64 * 128);
    const int r0 = b * 64;

    for (int half = 0; half < 2; half++) {
        const float* bias = half ? b_oah : b_iah;
        __syncthreads();
        for (int i = tid; i < 64 * 64; i += 256) {
            int n = i >> 6, m = i & 63;
            shA[i] = Ab[n * 128 + half * 64 + m];
        }
        for (int chunk = 0; chunk < 2; chunk++) {
            __syncthreads();
            for (int i = tid; i < 64 * 128; i += 256) {
                int m = i >> 7, c = i & 127;
                shH[i] = g_hcat[(size_t)(r0 + m) * 512 + half * 256 + chunk * 128 + c];
            }
            __syncthreads();
            for (int tIdx = tid; tIdx < 512; tIdx += 256) {
                int n = (tIdx >> 5) * 4;
                int c = (tIdx & 31) * 4;
                float acc[4][4];
                #pragma unroll
                for (int i = 0; i < 4; i++)
                    #pragma unroll
                    for (int j = 0; j < 4; j++) acc[i][j] = 0.f;
                #pragma unroll 4
                for (int m = 0; m < 64; m++) {
                    float4 hv = *(const float4*)&shH[m * 128 + c];
                    float a0 = shA[(n + 0) * 64 + m];
                    float a1 = shA[(n + 1) * 64 + m];
                    float a2 = shA[(n + 2) * 64 + m];
                    float a3 = shA[(n + 3) * 64 + m];
                    acc[0][0] += a0 * hv.x; acc[0][1] += a0 * hv.y; acc[0][2] += a0 * hv.z; acc[0][3] += a0 * hv.w;
                    acc[1][0] += a1 * hv.x; acc[1][1] += a1 * hv.y; acc[1][2] += a1 * hv.z; acc[1][3] += a1 * hv.w;
                    acc[2][0] += a2 * hv.x; acc[2][1] += a2 * hv.y; acc[2][2] += a2 * hv.z; acc[2][3] += a2 * hv.w;
                    acc[3][0] += a3 * hv.x; acc[3][1] += a3 * hv.y; acc[3][2] += a3 * hv.z; acc[3][3] += a3 * hv.w;
                }
                int cc = chunk * 128 + c;
                float b0 = bias[cc + 0], b1 = bias[cc + 1], b2 = bias[cc + 2], b3 = bias[cc + 3];
                #pragma unroll
                for (int i = 0; i < 4; i++) {
                    float4 o;
                    o.x = tf32_rna(acc[i][0] + b0); o.y = tf32_rna(acc[i][1] + b1);
                    o.z = tf32_rna(acc[i][2] + b2); o.w = tf32_rna(acc[i][3] + b3);
                    *(float4*)&g_X[(size_t)(r0 + n + i) * KX + half * 256 + cc] = o;
                }
            }
        }
    }
}

// ---------------- K5: gates epilogue -> out ----------------
__global__ void __launch_bounds__(256) gates_kernel(float* __restrict__ out)
{
    int idx = blockIdx.x * blockDim.x + threadIdx.x;
    if (idx >= BN_ * H_) return;
    int r = idx >> 8;
    int c = idx & 255;
    const float* Gr = g_G + (size_t)r * NG;
    float sr  = Gr[c];
    float si  = Gr[256 + c];
    float vin = Gr[512 + c];
    float vhn = Gr[768 + c];
    float h   = g_X[(size_t)r * KX + 512 + c];
    float rg = 1.f / (1.f + expf(-sr));
    float ig = 1.f / (1.f + expf(-si));
    float ng = tanhf(vin + rg * vhn);
    out[idx] = ng + ig * (h - ng);
}

// ---------------- launcher ----------------
extern "C" void kernel_launch(void* const* d_in, const int* in_sizes, int n_in,
                              void* d_out, int out_size)
{
    const int*   inputs = (const int*)  d_in[0];   // [512,64]
    const float* Aadj   = (const float*)d_in[1];   // [512,64,128]
    const float* emb    = (const float*)d_in[2];   // [100000,256]
    const float* W_in   = (const float*)d_in[3];
    const float* b_in   = (const float*)d_in[4];
    const float* W_out  = (const float*)d_in[5];
    const float* b_out  = (const float*)d_in[6];
    const float* w_ih   = (const float*)d_in[7];   // [768,512]
    const float* b_ih   = (const float*)d_in[8];
    const float* w_hh   = (const float*)d_in[9];   // [768,256]
    const float* b_hh   = (const float*)d_in[10];
    const float* b_iah  = (const float*)d_in[11];
    const float* b_oah  = (const float*)d_in[12];
    float* out = (float*)d_out;

    float *d_X, *d_hcat, *d_G, *d_Wpack, *d_bpack, *d_Wcat, *d_bcat;
    cudaGetSymbolAddress((void**)&d_X, g_X);
    cudaGetSymbolAddress((void**)&d_hcat, g_hcat);
    cudaGetSymbolAddress((void**)&d_G, g_G);
    cudaGetSymbolAddress((void**)&d_Wpack, g_Wpack);
    cudaGetSymbolAddress((void**)&d_bpack, g_bpack);
    cudaGetSymbolAddress((void**)&d_Wcat, g_Wcat);
    cudaGetSymbolAddress((void**)&d_bcat, g_bcat);

    static int smem_set = 0;
    if (!smem_set) {
        cudaFuncSetAttribute(mma_gemm_tf32,
                             cudaFuncAttributeMaxDynamicSharedMemorySize,
                             2 * STAGE_FLTS * (int)sizeof(float));
        smem_set = 1;
    }
    const int smemBytes = 2 * STAGE_FLTS * (int)sizeof(float);  // 73728

    // K0: pack weights (tf32-rounded)
    build_pack<<<512, 256>>>(w_ih, w_hh, b_ih, b_hh, W_in, b_in, W_out, b_out);

    // K1: gather + normalize into X[:,512:768] (tf32-rounded)
    gather_norm<<<BN_, 256>>>(inputs, emb);

    // K2: hcat = h @ Wcat^T + bcat   (M=32768, N=512, K=256) — tensor core
    mma_gemm_tf32<<<dim3(BN_ / 128, 512 / 128), 256, smemBytes>>>(
        d_X + 512, KX, d_Wcat, H_, d_bcat, d_hcat, 512, 0, 256, 0);

    // K3: adjacency -> X[:,0:512] (tf32-rounded outputs)
    adjacency_kernel<<<B_, 256>>>(Aadj, b_iah, b_oah);

    // K4: G = X @ Wpack^T + bpack   (grouped K ranges) — tensor core
    mma_gemm_tf32<<<dim3(BN_ / 128, NG / 128), 256, smemBytes>>>(
        d_X, KX, d_Wpack, KX, d_bpack, d_G, NG, 0, 0, 1);

    // K5: gates
    gates_kernel<<<(BN_ * H_ + 255) / 256, 256>>>(out);
}

// round 4
// speedup vs baseline: 3.6871x; 1.5006x over previous
#include <cuda_runtime.h>
#include <cuda_fp16.h>
#include <math.h>
#include <stdint.h>

// Problem constants
#define B_    512
#define N_    64
#define H_    256
#define BN_   32768          // B_*N_
#define KX    768            // X = [inp(512) | h(256)]
#define NG    1024           // G columns: [r-sum 256 | i-sum 256 | i_n 256 | h_n 256]

// ---------------- device scratch (static, allocation-free) ----------------
__device__ __half g_X[(size_t)BN_ * KX];        // fp16 activations [32768,768]
__device__ float  g_hcat[(size_t)BN_ * 512];    // [32768,512] = [hin | hout]
__device__ float  g_G[(size_t)BN_ * NG];        // [32768,1024]
__device__ __half g_Wpack[NG * KX];             // packed big weight [1024,768] fp16
__device__ float  g_bpack[NG];
__device__ __half g_Wcat[512 * H_];             // [W_in; W_out] rows fp16
__device__ float  g_bcat[512];

// ---------------- K0: pack weights/biases (fp16 weights) ----------
__global__ void build_pack(const float* __restrict__ w_ih, const float* __restrict__ w_hh,
                           const float* __restrict__ b_ih, const float* __restrict__ b_hh,
                           const float* __restrict__ W_in, const float* __restrict__ b_in,
                           const float* __restrict__ W_out, const float* __restrict__ b_out)
{
    const int stride = gridDim.x * blockDim.x;
    const int idx = blockIdx.x * blockDim.x + threadIdx.x;

    for (int i = idx; i < NG * KX; i += stride) {
        int n = i / KX, k = i - n * KX;
        float v = 0.f;
        if (n < 512)      v = (k < 512) ? w_ih[n * 512 + k] : w_hh[n * 256 + (k - 512)];
        else if (n < 768) v = (k < 512) ? w_ih[n * 512 + k] : 0.f;
        else              v = (k >= 512) ? w_hh[(n - 256) * 256 + (k - 512)] : 0.f;
        g_Wpack[i] = __float2half_rn(v);
    }
    for (int i = idx; i < 512 * H_; i += stride) {
        float v = (i < 256 * H_) ? W_in[i] : W_out[i - 256 * H_];
        g_Wcat[i] = __float2half_rn(v);
    }
    for (int i = idx; i < NG; i += stride) {
        float bv;
        if (i < 512)      bv = b_ih[i] + b_hh[i];
        else if (i < 768) bv = b_ih[i];
        else              bv = b_hh[i - 256];
        g_bpack[i] = bv;
    }
    for (int i = idx; i < 512; i += stride)
        g_bcat[i] = (i < 256) ? b_in[i] : b_out[i - 256];
}

// ---------------- K1: embedding gather + L2 normalize -> g_X[:,512:768] ----
__global__ void __launch_bounds__(256) gather_norm(const int* __restrict__ inputs,
                                                   const float* __restrict__ emb)
{
    const int row = blockIdx.x;
    const int t = threadIdx.x;
    const float* e = emb + (size_t)inputs[row] * H_;
    float v = e[t];
    float ss = v * v;
    #pragma unroll
    for (int o = 16; o > 0; o >>= 1) ss += __shfl_xor_sync(0xffffffffu, ss, o);
    __shared__ float ws[8];
    __shared__ float s_scale;
    if ((t & 31) == 0) ws[t >> 5] = ss;
    __syncthreads();
    if (t == 0) {
        float s = 0.f;
        #pragma unroll
        for (int i = 0; i < 8; i++) s += ws[i];
        s_scale = 1.f / (sqrtf(s) + 1e-12f);
    }
    __syncthreads();
    g_X[(size_t)row * KX + 512 + t] = __float2half_rn(v * s_scale);
}

// ---------------- cp.async helpers ----------------
__device__ __forceinline__ void cp_async16(void* smem_dst, const void* gmem_src) {
    uint32_t sa = (uint32_t)__cvta_generic_to_shared(smem_dst);
    asm volatile("cp.async.cg.shared.global [%0], [%1], 16;\n" :: "r"(sa), "l"(gmem_src));
}
__device__ __forceinline__ void cp_commit() { asm volatile("cp.async.commit_group;\n"); }

// ---------------- FP16 tensor-core GEMM (NT): C[m,n] = sum_k A[m,k]*B[n,k] + bias[n]
// CTA tile 128x128, BK=64 halves, 256 threads (8 warps), warp tile 64x32
// (4x4 grid of m16n8k16). Smem rows padded: 64 halves data + 8 pad = 36 u32.
#define SM_STRIDE 36                     // u32 words per smem row
#define TILE_U32 (128 * SM_STRIDE)       // 4608 u32 per tile
#define STAGE_U32 (2 * TILE_U32)         // A + B per stage

__global__ void __launch_bounds__(256, 2) mma_gemm_f16(
    const __half* __restrict__ Am, int lda,
    const __half* __restrict__ Bm, int ldb,
    const float* __restrict__ bias,
    float* __restrict__ C, int ldc,
    int kBegin, int kEnd, int grouped)
{
    extern __shared__ uint32_t sm[];   // 2 stages * (As + Bs)

    const int tid = threadIdx.x;
    const int m0 = blockIdx.x * 128;
    const int n0 = blockIdx.y * 128;

    int kb = kBegin, ke = kEnd;
    if (grouped) {
        if (n0 >= 768)      { kb = 512; ke = 768; }   // h_n : K over h part
        else if (n0 >= 512) { kb = 0;   ke = 512; }   // i_n : K over inp part
        else                { kb = 0;   ke = 768; }   // r/i sums : full K
    }

    const int lane = tid & 31;
    const int g = lane >> 2;      // 0..7
    const int t = lane & 3;       // 0..3
    const int warpId = tid >> 5;
    const int wm = (warpId >> 2) * 64;   // 0 or 64
    const int wn = (warpId & 3) * 32;    // 0..96

    // global->smem: row = tid>>1 (0..127), each thread 4 chunks of 16B
    const int ldr = tid >> 1;
    const int ldh = (tid & 1) * 32;      // half-offset within 64-half row

    const __half* gA = Am + (size_t)(m0 + ldr) * lda + ldh;
    const __half* gB = Bm + (size_t)(n0 + ldr) * ldb + ldh;
    const int sOff = ldr * SM_STRIDE + (tid & 1) * 16;  // u32 offset

    float acc[4][4][4];
    #pragma unroll
    for (int i = 0; i < 4; i++)
        #pragma unroll
        for (int j = 0; j < 4; j++)
            #pragma unroll
            for (int c = 0; c < 4; c++) acc[i][j][c] = 0.f;

    // prologue: stage 0
    {
        uint32_t* As = sm;
        uint32_t* Bs = sm + TILE_U32;
        #pragma unroll
        for (int j = 0; j < 4; j++) {
            cp_async16(As + sOff + j * 4, gA + kb + j * 8);
            cp_async16(Bs + sOff + j * 4, gB + kb + j * 8);
        }
        cp_commit();
    }

    int s = 0;
    for (int k0 = kb; k0 < ke; k0 += 64, s ^= 1) {
        asm volatile("cp.async.wait_group 0;\n" ::: "memory");
        __syncthreads();

        const int kn = k0 + 64;
        if (kn < ke) {
            uint32_t* As = sm + (s ^ 1) * STAGE_U32;
            uint32_t* Bs = As + TILE_U32;
            #pragma unroll
            for (int j = 0; j < 4; j++) {
                cp_async16(As + sOff + j * 4, gA + kn + j * 8);
                cp_async16(Bs + sOff + j * 4, gB + kn + j * 8);
            }
            cp_commit();
        }

        const uint32_t* As = sm + s * STAGE_U32;
        const uint32_t* Bs = As + TILE_U32;

        #pragma unroll
        for (int kk = 0; kk < 4; kk++) {
            const int k8 = kk * 8;       // u32 offset = 16 halves per step
            uint32_t a[4][4];
            #pragma unroll
            for (int mt = 0; mt < 4; mt++) {
                const int row = wm + mt * 16 + g;
                a[mt][0] = As[row * SM_STRIDE + k8 + t];
                a[mt][1] = As[(row + 8) * SM_STRIDE + k8 + t];
                a[mt][2] = As[row * SM_STRIDE + k8 + t + 4];
                a[mt][3] = As[(row + 8) * SM_STRIDE + k8 + t + 4];
            }
            uint32_t b[4][2];
            #pragma unroll
            for (int nt = 0; nt < 4; nt++) {
                const int col = wn + nt * 8 + g;
                b[nt][0] = Bs[col * SM_STRIDE + k8 + t];
                b[nt][1] = Bs[col * SM_STRIDE + k8 + t + 4];
            }
            #pragma unroll
            for (int mt = 0; mt < 4; mt++)
                #pragma unroll
                for (int nt = 0; nt < 4; nt++) {
                    asm volatile(
                        "mma.sync.aligned.m16n8k16.row.col.f32.f16.f16.f32 "
                        "{%0,%1,%2,%3}, {%4,%5,%6,%7}, {%8,%9}, {%0,%1,%2,%3};\n"
                        : "+f"(acc[mt][nt][0]), "+f"(acc[mt][nt][1]),
                          "+f"(acc[mt][nt][2]), "+f"(acc[mt][nt][3])
                        : "r"(a[mt][0]), "r"(a[mt][1]), "r"(a[mt][2]), "r"(a[mt][3]),
                          "r"(b[nt][0]), "r"(b[nt][1]));
                }
        }
        __syncthreads();
    }

    // epilogue: bias add + store
    #pragma unroll
    for (int nt = 0; nt < 4; nt++) {
        const int col = n0 + wn + nt * 8 + t * 2;
        const float b0 = bias[col], b1 = bias[col + 1];
        #pragma unroll
        for (int mt = 0; mt < 4; mt++) {
            const int row = m0 + wm + mt * 16 + g;
            float2 o0, o1;
            o0.x = acc[mt][nt][0] + b0; o0.y = acc[mt][nt][1] + b1;
            o1.x = acc[mt][nt][2] + b0; o1.y = acc[mt][nt][3] + b1;
            *(float2*)(C + (size_t)row * ldc + col) = o0;
            *(float2*)(C + (size_t)(row + 8) * ldc + col) = o1;
        }
    }
}

// ---------------- K3: per-batch adjacency matmuls -> g_X[:,0:512] ----------
__global__ void __launch_bounds__(256) adjacency_kernel(const float* __restrict__ Aadj,
                                                        const float* __restrict__ b_iah,
                                                        const float* __restrict__ b_oah)
{
    __shared__ float shA[64 * 64];
    __shared__ float shH[64 * 128];
    const int b = blockIdx.x;
    const int tid = threadIdx.x;
    const float* Ab = Aadj + (size_t)b * (64 * 128);
    const int r0 = b * 64;

    for (int half = 0; half < 2; half++) {
        const float* bias = half ? b_oah : b_iah;
        __syncthreads();
        for (int i = tid; i < 64 * 64; i += 256) {
            int n = i >> 6, m = i & 63;
            shA[i] = Ab[n * 128 + half * 64 + m];
        }
        for (int chunk = 0; chunk < 2; chunk++) {
            __syncthreads();
            for (int i = tid; i < 64 * 128; i += 256) {
                int m = i >> 7, c = i & 127;
                shH[i] = g_hcat[(size_t)(r0 + m) * 512 + half * 256 + chunk * 128 + c];
            }
            __syncthreads();
            for (int tIdx = tid; tIdx < 512; tIdx += 256) {
                int n = (tIdx >> 5) * 4;
                int c = (tIdx & 31) * 4;
                float acc[4][4];
                #pragma unroll
                for (int i = 0; i < 4; i++)
                    #pragma unroll
                    for (int j = 0; j < 4; j++) acc[i][j] = 0.f;
                #pragma unroll 4
                for (int m = 0; m < 64; m++) {
                    float4 hv = *(const float4*)&shH[m * 128 + c];
                    float a0 = shA[(n + 0) * 64 + m];
                    float a1 = shA[(n + 1) * 64 + m];
                    float a2 = shA[(n + 2) * 64 + m];
                    float a3 = shA[(n + 3) * 64 + m];
                    acc[0][0] += a0 * hv.x; acc[0][1] += a0 * hv.y; acc[0][2] += a0 * hv.z; acc[0][3] += a0 * hv.w;
                    acc[1][0] += a1 * hv.x; acc[1][1] += a1 * hv.y; acc[1][2] += a1 * hv.z; acc[1][3] += a1 * hv.w;
                    acc[2][0] += a2 * hv.x; acc[2][1] += a2 * hv.y; acc[2][2] += a2 * hv.z; acc[2][3] += a2 * hv.w;
                    acc[3][0] += a3 * hv.x; acc[3][1] += a3 * hv.y; acc[3][2] += a3 * hv.z; acc[3][3] += a3 * hv.w;
                }
                int cc = chunk * 128 + c;
                float b0 = bias[cc + 0], b1 = bias[cc + 1], b2 = bias[cc + 2], b3 = bias[cc + 3];
                #pragma unroll
                for (int i = 0; i < 4; i++) {
                    __half2 h0 = __floats2half2_rn(acc[i][0] + b0, acc[i][1] + b1);
                    __half2 h1 = __floats2half2_rn(acc[i][2] + b2, acc[i][3] + b3);
                    __half2* dst = (__half2*)&g_X[(size_t)(r0 + n + i) * KX + half * 256 + cc];
                    dst[0] = h0;
                    dst[1] = h1;
                }
            }
        }
    }
}

// ---------------- K5: gates epilogue -> out ----------------
__global__ void __launch_bounds__(256) gates_kernel(float* __restrict__ out)
{
    int idx = blockIdx.x * blockDim.x + threadIdx.x;
    if (idx >= BN_ * H_) return;
    int r = idx >> 8;
    int c = idx & 255;
    const float* Gr = g_G + (size_t)r * NG;
    float sr  = Gr[c];
    float si  = Gr[256 + c];
    float vin = Gr[512 + c];
    float vhn = Gr[768 + c];
    float h   = __half2float(g_X[(size_t)r * KX + 512 + c]);
    float rg = 1.f / (1.f + expf(-sr));
    float ig = 1.f / (1.f + expf(-si));
    float ng = tanhf(vin + rg * vhn);
    out[idx] = ng + ig * (h - ng);
}

// ---------------- launcher ----------------
extern "C" void kernel_launch(void* const* d_in, const int* in_sizes, int n_in,
                              void* d_out, int out_size)
{
    const int*   inputs = (const int*)  d_in[0];   // [512,64]
    const float* Aadj   = (const float*)d_in[1];   // [512,64,128]
    const float* emb    = (const float*)d_in[2];   // [100000,256]
    const float* W_in   = (const float*)d_in[3];
    const float* b_in   = (const float*)d_in[4];
    const float* W_out  = (const float*)d_in[5];
    const float* b_out  = (const float*)d_in[6];
    const float* w_ih   = (const float*)d_in[7];   // [768,512]
    const float* b_ih   = (const float*)d_in[8];
    const float* w_hh   = (const float*)d_in[9];   // [768,256]
    const float* b_hh   = (const float*)d_in[10];
    const float* b_iah  = (const float*)d_in[11];
    const float* b_oah  = (const float*)d_in[12];
    float* out = (float*)d_out;

    __half *d_X, *d_Wpack, *d_Wcat;
    float *d_hcat, *d_G, *d_bpack, *d_bcat;
    cudaGetSymbolAddress((void**)&d_X, g_X);
    cudaGetSymbolAddress((void**)&d_hcat, g_hcat);
    cudaGetSymbolAddress((void**)&d_G, g_G);
    cudaGetSymbolAddress((void**)&d_Wpack, g_Wpack);
    cudaGetSymbolAddress((void**)&d_bpack, g_bpack);
    cudaGetSymbolAddress((void**)&d_Wcat, g_Wcat);
    cudaGetSymbolAddress((void**)&d_bcat, g_bcat);

    static int smem_set = 0;
    if (!smem_set) {
        cudaFuncSetAttribute(mma_gemm_f16,
                             cudaFuncAttributeMaxDynamicSharedMemorySize,
                             2 * STAGE_U32 * (int)sizeof(uint32_t));
        smem_set = 1;
    }
    const int smemBytes = 2 * STAGE_U32 * (int)sizeof(uint32_t);  // 73728

    // K0: pack weights (fp16)
    build_pack<<<512, 256>>>(w_ih, w_hh, b_ih, b_hh, W_in, b_in, W_out, b_out);

    // K1: gather + normalize into X[:,512:768] (fp16)
    gather_norm<<<BN_, 256>>>(inputs, emb);

    // K2: hcat = h @ Wcat^T + bcat   (M=32768, N=512, K=256) — fp16 HMMA
    mma_gemm_f16<<<dim3(BN_ / 128, 512 / 128), 256, smemBytes>>>(
        d_X + 512, KX, d_Wcat, H_, d_bcat, d_hcat, 512, 0, 256, 0);

    // K3: adjacency -> X[:,0:512] (fp16 outputs)
    adjacency_kernel<<<B_, 256>>>(Aadj, b_iah, b_oah);

    // K4: G = X @ Wpack^T + bpack   (grouped K ranges) — fp16 HMMA
    mma_gemm_f16<<<dim3(BN_ / 128, NG / 128), 256, smemBytes>>>(
        d_X, KX, d_Wpack, KX, d_bpack, d_G, NG, 0, 0, 1);

    // K5: gates
    gates_kernel<<<(BN_ * H_ + 255) / 256, 256>>>(out);
}

// round 5
// speedup vs baseline: 4.6406x; 1.2586x over previous
#include <cuda_runtime.h>
#include <cuda_fp16.h>
#include <math.h>
#include <stdint.h>

// Problem constants
#define B_    512
#define N_    64
#define H_    256
#define BN_   32768          // B_*N_
#define KX    768            // X = [inp(512) | h(256)]
#define NG    1024           // G columns: [r-sum 256 | i-sum 256 | i_n 256 | h_n 256]

// ---------------- device scratch (static, allocation-free) ----------------
__device__ __half g_X[(size_t)BN_ * KX];        // fp16 activations [32768,768]
__device__ __half g_hcat[(size_t)BN_ * 512];    // fp16 [32768,512] = [hin | hout]
__device__ __half g_G[(size_t)BN_ * NG];        // fp16 [32768,1024]
__device__ __half g_Wpack[NG * KX];             // packed big weight [1024,768] fp16
__device__ float  g_bpack[NG];
__device__ __half g_Wcat[512 * H_];             // [W_in; W_out] rows fp16
__device__ float  g_bcat[512];

// ---------------- K0: pack weights/biases (fp16 weights) ----------
__global__ void build_pack(const float* __restrict__ w_ih, const float* __restrict__ w_hh,
                           const float* __restrict__ b_ih, const float* __restrict__ b_hh,
                           const float* __restrict__ W_in, const float* __restrict__ b_in,
                           const float* __restrict__ W_out, const float* __restrict__ b_out)
{
    const int stride = gridDim.x * blockDim.x;
    const int idx = blockIdx.x * blockDim.x + threadIdx.x;

    for (int i = idx; i < NG * KX; i += stride) {
        int n = i / KX, k = i - n * KX;
        float v = 0.f;
        if (n < 512)      v = (k < 512) ? w_ih[n * 512 + k] : w_hh[n * 256 + (k - 512)];
        else if (n < 768) v = (k < 512) ? w_ih[n * 512 + k] : 0.f;
        else              v = (k >= 512) ? w_hh[(n - 256) * 256 + (k - 512)] : 0.f;
        g_Wpack[i] = __float2half_rn(v);
    }
    for (int i = idx; i < 512 * H_; i += stride) {
        float v = (i < 256 * H_) ? W_in[i] : W_out[i - 256 * H_];
        g_Wcat[i] = __float2half_rn(v);
    }
    for (int i = idx; i < NG; i += stride) {
        float bv;
        if (i < 512)      bv = b_ih[i] + b_hh[i];
        else if (i < 768) bv = b_ih[i];
        else              bv = b_hh[i - 256];
        g_bpack[i] = bv;
    }
    for (int i = idx; i < 512; i += stride)
        g_bcat[i] = (i < 256) ? b_in[i] : b_out[i - 256];
}

// ---------------- K1: embedding gather + L2 normalize -> g_X[:,512:768] ----
__global__ void __launch_bounds__(256) gather_norm(const int* __restrict__ inputs,
                                                   const float* __restrict__ emb)
{
    const int row = blockIdx.x;
    const int t = threadIdx.x;
    const float* e = emb + (size_t)inputs[row] * H_;
    float v = e[t];
    float ss = v * v;
    #pragma unroll
    for (int o = 16; o > 0; o >>= 1) ss += __shfl_xor_sync(0xffffffffu, ss, o);
    __shared__ float ws[8];
    __shared__ float s_scale;
    if ((t & 31) == 0) ws[t >> 5] = ss;
    __syncthreads();
    if (t == 0) {
        float s = 0.f;
        #pragma unroll
        for (int i = 0; i < 8; i++) s += ws[i];
        s_scale = 1.f / (sqrtf(s) + 1e-12f);
    }
    __syncthreads();
    g_X[(size_t)row * KX + 512 + t] = __float2half_rn(v * s_scale);
}

// ---------------- helpers ----------------
__device__ __forceinline__ void cp_async16(void* smem_dst, const void* gmem_src) {
    uint32_t sa = (uint32_t)__cvta_generic_to_shared(smem_dst);
    asm volatile("cp.async.cg.shared.global [%0], [%1], 16;\n" :: "r"(sa), "l"(gmem_src));
}
__device__ __forceinline__ void cp_commit() { asm volatile("cp.async.commit_group;\n"); }

__device__ __forceinline__ void ldm_x4(uint32_t& r0, uint32_t& r1, uint32_t& r2, uint32_t& r3,
                                       uint32_t addr) {
    asm volatile("ldmatrix.sync.aligned.m8n8.x4.shared.b16 {%0,%1,%2,%3}, [%4];"
                 : "=r"(r0), "=r"(r1), "=r"(r2), "=r"(r3) : "r"(addr));
}
__device__ __forceinline__ void ldm_x4_t(uint32_t& r0, uint32_t& r1, uint32_t& r2, uint32_t& r3,
                                         uint32_t addr) {
    asm volatile("ldmatrix.sync.aligned.m8n8.x4.trans.shared.b16 {%0,%1,%2,%3}, [%4];"
                 : "=r"(r0), "=r"(r1), "=r"(r2), "=r"(r3) : "r"(addr));
}
#define HMMA16816(ac, a0, a1, a2, a3, b0, b1)                                          \
    asm volatile(                                                                      \
        "mma.sync.aligned.m16n8k16.row.col.f32.f16.f16.f32 "                           \
        "{%0,%1,%2,%3}, {%4,%5,%6,%7}, {%8,%9}, {%0,%1,%2,%3};\n"                      \
        : "+f"((ac)[0]), "+f"((ac)[1]), "+f"((ac)[2]), "+f"((ac)[3])                   \
        : "r"(a0), "r"(a1), "r"(a2), "r"(a3), "r"(b0), "r"(b1))

// ---------------- FP16 tensor-core GEMM (NT): C[m,n] = sum_k A[m,k]*B[n,k] + bias[n]
// CTA tile 128x128, BK=64 halves, 256 threads (8 warps), warp tile 64x32
// (4x4 grid of m16n8k16). Smem rows: 64 halves data + pad -> stride 36 u32.
// Fragment loads via ldmatrix. Output stored as fp16.
#define SM_STRIDE 36                     // u32 words per smem row
#define TILE_U32 (128 * SM_STRIDE)       // 4608 u32 per tile
#define STAGE_U32 (2 * TILE_U32)         // A + B per stage

__global__ void __launch_bounds__(256, 2) mma_gemm_f16(
    const __half* __restrict__ Am, int lda,
    const __half* __restrict__ Bm, int ldb,
    const float* __restrict__ bias,
    __half* __restrict__ C, int ldc,
    int kBegin, int kEnd, int grouped)
{
    extern __shared__ uint32_t sm[];   // 2 stages * (As + Bs)
    const uint32_t smBase = (uint32_t)__cvta_generic_to_shared(sm);

    const int tid = threadIdx.x;
    const int m0 = blockIdx.x * 128;
    const int n0 = blockIdx.y * 128;

    int kb = kBegin, ke = kEnd;
    if (grouped) {
        if (n0 >= 768)      { kb = 512; ke = 768; }   // h_n : K over h part
        else if (n0 >= 512) { kb = 0;   ke = 512; }   // i_n : K over inp part
        else                { kb = 0;   ke = 768; }   // r/i sums : full K
    }

    const int lane = tid & 31;
    const int g = lane >> 2;
    const int t = lane & 3;
    const int warpId = tid >> 5;
    const int wm = (warpId >> 2) * 64;   // 0 or 64
    const int wn = (warpId & 3) * 32;    // 0..96

    // global->smem: row = tid>>1 (0..127), each thread 4 chunks of 16B
    const int ldr = tid >> 1;
    const int ldh = (tid & 1) * 32;
    const __half* gA = Am + (size_t)(m0 + ldr) * lda + ldh;
    const __half* gB = Bm + (size_t)(n0 + ldr) * ldb + ldh;
    const int sOff = ldr * SM_STRIDE + (tid & 1) * 16;

    // ldmatrix per-thread byte offsets within a tile
    const uint32_t aOff = (uint32_t)(((wm + (lane & 15)) * SM_STRIDE + (lane >> 4) * 4) * 4);
    const uint32_t bOff = (uint32_t)(((wn + (lane >> 4) * 8 + (lane & 7)) * SM_STRIDE
                                      + ((lane >> 3) & 1) * 4) * 4);

    float acc[4][4][4];
    #pragma unroll
    for (int i = 0; i < 4; i++)
        #pragma unroll
        for (int j = 0; j < 4; j++)
            #pragma unroll
            for (int c = 0; c < 4; c++) acc[i][j][c] = 0.f;

    {   // prologue stage 0
        uint32_t* As = sm;
        uint32_t* Bs = sm + TILE_U32;
        #pragma unroll
        for (int j = 0; j < 4; j++) {
            cp_async16(As + sOff + j * 4, gA + kb + j * 8);
            cp_async16(Bs + sOff + j * 4, gB + kb + j * 8);
        }
        cp_commit();
    }

    int s = 0;
    for (int k0 = kb; k0 < ke; k0 += 64, s ^= 1) {
        asm volatile("cp.async.wait_group 0;\n" ::: "memory");
        __syncthreads();

        const int kn = k0 + 64;
        if (kn < ke) {
            uint32_t* As = sm + (s ^ 1) * STAGE_U32;
            uint32_t* Bs = As + TILE_U32;
            #pragma unroll
            for (int j = 0; j < 4; j++) {
                cp_async16(As + sOff + j * 4, gA + kn + j * 8);
                cp_async16(Bs + sOff + j * 4, gB + kn + j * 8);
            }
            cp_commit();
        }

        const uint32_t As_b = smBase + s * (STAGE_U32 * 4);
        const uint32_t Bs_b = As_b + TILE_U32 * 4;

        #pragma unroll
        for (int kk = 0; kk < 4; kk++) {
            uint32_t a[4][4];
            #pragma unroll
            for (int mt = 0; mt < 4; mt++)
                ldm_x4(a[mt][0], a[mt][1], a[mt][2], a[mt][3],
                       As_b + aOff + mt * (16 * SM_STRIDE * 4) + kk * 32);
            uint32_t b[4][2];
            ldm_x4(b[0][0], b[0][1], b[1][0], b[1][1], Bs_b + bOff + kk * 32);
            ldm_x4(b[2][0], b[2][1], b[3][0], b[3][1],
                   Bs_b + bOff + 2 * (8 * SM_STRIDE * 4) + kk * 32);

            #pragma unroll
            for (int mt = 0; mt < 4; mt++)
                #pragma unroll
                for (int nt = 0; nt < 4; nt++)
                    HMMA16816(acc[mt][nt], a[mt][0], a[mt][1], a[mt][2], a[mt][3],
                              b[nt][0], b[nt][1]);
        }
        __syncthreads();
    }

    // epilogue: bias add + fp16 store
    #pragma unroll
    for (int nt = 0; nt < 4; nt++) {
        const int col = n0 + wn + nt * 8 + t * 2;
        const float b0 = bias[col], b1 = bias[col + 1];
        #pragma unroll
        for (int mt = 0; mt < 4; mt++) {
            const int row = m0 + wm + mt * 16 + g;
            *(__half2*)(C + (size_t)row * ldc + col) =
                __floats2half2_rn(acc[mt][nt][0] + b0, acc[mt][nt][1] + b1);
            *(__half2*)(C + (size_t)(row + 8) * ldc + col) =
                __floats2half2_rn(acc[mt][nt][2] + b0, acc[mt][nt][3] + b1);
        }
    }
}

// ---------------- K3: per-batch adjacency matmuls (tensor cores) ----------
// out[n][c] = sum_m A[n][m] * hin[m][c] + bias[c]   (mma: M=n, K=m, N=c)
#define SA_STRIDE 36      // u32: 64 halves + pad
#define SH_STRIDE 68      // u32: 128 halves + pad
__global__ void __launch_bounds__(256) adjacency_mma(const float* __restrict__ Aadj,
                                                     const float* __restrict__ b_iah,
                                                     const float* __restrict__ b_oah)
{
    __shared__ __align__(16) uint32_t shA[64 * SA_STRIDE];   // [n][m] fp16
    __shared__ __align__(16) uint32_t shH[64 * SH_STRIDE];   // [m][c] fp16
    const int b = blockIdx.x;
    const int tid = threadIdx.x;
    const int lane = tid & 31;
    const int wid = tid >> 5;
    const int mw = wid >> 2;           // 0..1 -> n-rows block of 32
    const int nw = wid & 3;            // 0..3 -> c-cols block of 32
    const int g = lane >> 2;
    const int t = lane & 3;
    const float* Ab = Aadj + (size_t)b * (64 * 128);
    const int r0 = b * 64;

    const uint32_t shA_b = (uint32_t)__cvta_generic_to_shared(shA);
    const uint32_t shH_b = (uint32_t)__cvta_generic_to_shared(shH);
    const uint32_t aOff = (uint32_t)(((mw * 32 + (lane & 15)) * SA_STRIDE + (lane >> 4) * 4) * 4);
    const uint32_t hOff = (uint32_t)(((lane & 15) * SH_STRIDE + nw * 16 + (lane >> 4) * 4) * 4);

    for (int half = 0; half < 2; half++) {
        const float* bias = half ? b_oah : b_iah;
        __syncthreads();   // shA safe to overwrite
        // load A half: 64x64 fp32 -> fp16
        for (int i = tid; i < 64 * 32; i += 256) {
            int n = i >> 5, m2 = (i & 31) * 2;
            float2 v = *(const float2*)&Ab[n * 128 + half * 64 + m2];
            *(__half2*)&shA[n * SA_STRIDE + m2 / 2] = __floats2half2_rn(v.x, v.y);
        }
        for (int chunk = 0; chunk < 2; chunk++) {
            __syncthreads();   // shH safe to overwrite (also orders shA stores)
            for (int i = tid; i < 64 * 16; i += 256) {
                int m = i >> 4, c8 = (i & 15) * 8;
                uint4 v = *(const uint4*)&g_hcat[(size_t)(r0 + m) * 512
                                                 + half * 256 + chunk * 128 + c8];
                *(uint4*)&shH[m * SH_STRIDE + c8 / 2] = v;
            }
            __syncthreads();

            float acc[2][4][4];
            #pragma unroll
            for (int i = 0; i < 2; i++)
                #pragma unroll
                for (int j = 0; j < 4; j++)
                    #pragma unroll
                    for (int c = 0; c < 4; c++) acc[i][j][c] = 0.f;

            #pragma unroll
            for (int kk = 0; kk < 4; kk++) {
                uint32_t a[2][4];
                #pragma unroll
                for (int mt = 0; mt < 2; mt++)
                    ldm_x4(a[mt][0], a[mt][1], a[mt][2], a[mt][3],
                           shA_b + aOff + mt * (16 * SA_STRIDE * 4) + kk * 32);
                uint32_t bb[4][2];
                ldm_x4_t(bb[0][0], bb[0][1], bb[1][0], bb[1][1],
                         shH_b + hOff + kk * (16 * SH_STRIDE * 4));
                ldm_x4_t(bb[2][0], bb[2][1], bb[3][0], bb[3][1],
                         shH_b + hOff + kk * (16 * SH_STRIDE * 4) + 2 * 16);
                #pragma unroll
                for (int mt = 0; mt < 2; mt++)
                    #pragma unroll
                    for (int nt = 0; nt < 4; nt++)
                        HMMA16816(acc[mt][nt], a[mt][0], a[mt][1], a[mt][2], a[mt][3],
                                  bb[nt][0], bb[nt][1]);
            }

            // store to g_X[:, half*256 + chunk*128 + c] as fp16
            #pragma unroll
            for (int nt = 0; nt < 4; nt++) {
                const int c = nw * 32 + nt * 8 + t * 2;
                const int cc = chunk * 128 + c;
                const float b0 = bias[cc], b1 = bias[cc + 1];
                #pragma unroll
                for (int mt = 0; mt < 2; mt++) {
                    const int n = mw * 32 + mt * 16 + g;
                    __half* dst = g_X + (size_t)(r0 + n) * KX + half * 256 + cc;
                    *(__half2*)dst = __floats2half2_rn(acc[mt][nt][0] + b0,
                                                       acc[mt][nt][1] + b1);
                    __half* dst8 = g_X + (size_t)(r0 + n + 8) * KX + half * 256 + cc;
                    *(__half2*)dst8 = __floats2half2_rn(acc[mt][nt][2] + b0,
                                                        acc[mt][nt][3] + b1);
                }
            }
        }
    }
}

// ---------------- K5: gates epilogue -> out (fp32) ----------------
__global__ void __launch_bounds__(256) gates_kernel(float* __restrict__ out)
{
    int idx = blockIdx.x * blockDim.x + threadIdx.x;   // over BN_*128
    if (idx >= BN_ * 128) return;
    int r = idx >> 7;
    int c = (idx & 127) << 1;
    const __half* Gr = g_G + (size_t)r * NG;
    float2 sr  = __half22float2(*(const __half2*)&Gr[c]);
    float2 si  = __half22float2(*(const __half2*)&Gr[256 + c]);
    float2 vin = __half22float2(*(const __half2*)&Gr[512 + c]);
    float2 vhn = __half22float2(*(const __half2*)&Gr[768 + c]);
    float2 h   = __half22float2(*(const __half2*)&g_X[(size_t)r * KX + 512 + c]);

    float rg0 = 1.f / (1.f + expf(-sr.x)), rg1 = 1.f / (1.f + expf(-sr.y));
    float ig0 = 1.f / (1.f + expf(-si.x)), ig1 = 1.f / (1.f + expf(-si.y));
    float ng0 = tanhf(vin.x + rg0 * vhn.x), ng1 = tanhf(vin.y + rg1 * vhn.y);
    float2 o;
    o.x = ng0 + ig0 * (h.x - ng0);
    o.y = ng1 + ig1 * (h.y - ng1);
    *(float2*)(out + (size_t)r * H_ + c) = o;
}

// ---------------- launcher ----------------
extern "C" void kernel_launch(void* const* d_in, const int* in_sizes, int n_in,
                              void* d_out, int out_size)
{
    const int*   inputs = (const int*)  d_in[0];   // [512,64]
    const float* Aadj   = (const float*)d_in[1];   // [512,64,128]
    const float* emb    = (const float*)d_in[2];   // [100000,256]
    const float* W_in   = (const float*)d_in[3];
    const float* b_in   = (const float*)d_in[4];
    const float* W_out  = (const float*)d_in[5];
    const float* b_out  = (const float*)d_in[6];
    const float* w_ih   = (const float*)d_in[7];   // [768,512]
    const float* b_ih   = (const float*)d_in[8];
    const float* w_hh   = (const float*)d_in[9];   // [768,256]
    const float* b_hh   = (const float*)d_in[10];
    const float* b_iah  = (const float*)d_in[11];
    const float* b_oah  = (const float*)d_in[12];
    float* out = (float*)d_out;

    __half *d_X, *d_Wpack, *d_Wcat, *d_hcat, *d_G;
    float *d_bpack, *d_bcat;
    cudaGetSymbolAddress((void**)&d_X, g_X);
    cudaGetSymbolAddress((void**)&d_hcat, g_hcat);
    cudaGetSymbolAddress((void**)&d_G, g_G);
    cudaGetSymbolAddress((void**)&d_Wpack, g_Wpack);
    cudaGetSymbolAddress((void**)&d_bpack, g_bpack);
    cudaGetSymbolAddress((void**)&d_Wcat, g_Wcat);
    cudaGetSymbolAddress((void**)&d_bcat, g_bcat);

    static int smem_set = 0;
    if (!smem_set) {
        cudaFuncSetAttribute(mma_gemm_f16,
                             cudaFuncAttributeMaxDynamicSharedMemorySize,
                             2 * STAGE_U32 * (int)sizeof(uint32_t));
        smem_set = 1;
    }
    const int smemBytes = 2 * STAGE_U32 * (int)sizeof(uint32_t);  // 73728

    // K0: pack weights (fp16)
    build_pack<<<512, 256>>>(w_ih, w_hh, b_ih, b_hh, W_in, b_in, W_out, b_out);

    // K1: gather + normalize into X[:,512:768] (fp16)
    gather_norm<<<BN_, 256>>>(inputs, emb);

    // K2: hcat = h @ Wcat^T + bcat   (M=32768, N=512, K=256) — fp16 HMMA
    mma_gemm_f16<<<dim3(BN_ / 128, 512 / 128), 256, smemBytes>>>(
        d_X + 512, KX, d_Wcat, H_, d_bcat, d_hcat, 512, 0, 256, 0);

    // K3: adjacency -> X[:,0:512] — fp16 HMMA
    adjacency_mma<<<B_, 256>>>(Aadj, b_iah, b_oah);

    // K4: G = X @ Wpack^T + bpack   (grouped K ranges) — fp16 HMMA
    mma_gemm_f16<<<dim3(BN_ / 128, NG / 128), 256, smemBytes>>>(
        d_X, KX, d_Wpack, KX, d_bpack, d_G, NG, 0, 0, 1);

    // K5: gates
    gates_kernel<<<(BN_ * 128 + 255) / 256, 256>>>(out);
}